// round 11
// baseline (speedup 1.0000x reference)
#include <cuda_runtime.h>

#define LSEQ    2048
#define BATCH   32
#define NPAIR   1024
#define TPB     128
#define NCHUNK  8
#define UPC     128           // query-pairs per chunk (256 queries)
#define NSEG    8
#define SEGMAX  128           // max pairs per segment: (7+1)*16
#define DT_C    0.01f
#define EPS_C   1e-5f
#define QS_C    (1.4426950408889634f * 0.57735026918962576f)  // log2e/sqrt(3)

typedef unsigned long long ull;

__device__ __forceinline__ ull fma2(ull a, ull b, ull c) {
    ull d; asm("fma.rn.f32x2 %0, %1, %2, %3;" : "=l"(d) : "l"(a), "l"(b), "l"(c)); return d;
}
__device__ __forceinline__ ull mul2(ull a, ull b) {
    ull d; asm("mul.rn.f32x2 %0, %1, %2;" : "=l"(d) : "l"(a), "l"(b)); return d;
}
__device__ __forceinline__ ull add2(ull a, ull b) {
    ull d; asm("add.rn.f32x2 %0, %1, %2;" : "=l"(d) : "l"(a), "l"(b)); return d;
}
__device__ __forceinline__ ull pk2(float lo, float hi) {
    ull r; asm("mov.b64 %0, {%1, %2};" : "=l"(r) : "f"(lo), "f"(hi)); return r;
}
__device__ __forceinline__ void up2(ull v, float& lo, float& hi) {
    asm("mov.b64 {%0, %1}, %2;" : "=f"(lo), "=f"(hi) : "l"(v));
}
__device__ __forceinline__ float ex2f(float x) {
    float y; asm("ex2.approx.ftz.f32 %0, %1;" : "=f"(y) : "f"(x)); return y;
}

// partials [b][q][seg] + per-query-pair arrival counters (zero-init, reset by winner)
__device__ float4   g_part[BATCH][LSEQ][NSEG];
__device__ unsigned g_cnt[BATCH][NPAIR];

__global__ void __launch_bounds__(TPB, 6)
attn_kernel(const float* __restrict__ inp,
            const float* __restrict__ ipw, const float* __restrict__ ipb,
            const float* __restrict__ opw, const float* __restrict__ opb,
            const float* __restrict__ f1w, const float* __restrict__ f1b,
            const float* __restrict__ f2w, const float* __restrict__ f2b,
            const float* __restrict__ g1w, const float* __restrict__ g1b,
            const float* __restrict__ g2w, const float* __restrict__ g2b,
            const float* __restrict__ m1p, const float* __restrict__ m2p,
            const float* __restrict__ sig,
            float* __restrict__ out)
{
    __shared__ float4 sP[SEGMAX];   // (k0e,k0o,k1e,k1o), relative index
    __shared__ float4 sQ[SEGMAX];   // (k2e,k2o,v0e,v0o)
    __shared__ float4 sR[SEGMAX];   // (v1e,v1o,v2e,v2o)

    const int b = blockIdx.x;
    const int s = blockIdx.y;
    const int c = (NCHUNK - 1) - blockIdx.z;      // long chunks first
    const int t = threadIdx.x;
    const int u = c * UPC + t;                    // query-pair id; qa=2u, qb=2u+1

    const int segl = (c + 1) * (UPC / NSEG);      // (c+1)*16 pairs
    const int s0 = s * segl;

    const float inv0 = 1.0f / (__ldg(&sig[0]) + EPS_C);
    const float inv1 = 1.0f / (__ldg(&sig[1]) + EPS_C);
    const float* xb = inp + ((size_t)b * LSEQ) * 3;

    // ---- project this segment's K/V pairs into smem ----
    {
        float WK[9], WV[9], BK[3], BV[3];
        #pragma unroll
        for (int k = 0; k < 9; k++) { WK[k] = __ldg(&ipw[9 + k]); WV[k] = __ldg(&ipw[18 + k]); }
        #pragma unroll
        for (int k = 0; k < 3; k++) { BK[k] = __ldg(&ipb[3 + k]); BV[k] = __ldg(&ipb[6 + k]); }

        for (int j = t; j < segl; j += TPB) {
            const float2* xp = (const float2*)(xb + 6 * (s0 + j));
            float2 u0 = __ldg(&xp[0]);
            float2 u1 = __ldg(&xp[1]);
            float2 u2 = __ldg(&xp[2]);
            float xe0 = u0.x, xe1 = u0.y * inv0, xe2 = u1.x * inv1;
            float xo0 = u1.y, xo1 = u2.x * inv0, xo2 = u2.y * inv1;
            float ke[3], ko[3], ve[3], vo[3];
            #pragma unroll
            for (int r = 0; r < 3; r++) {
                ke[r] = fmaf(WK[3*r], xe0, fmaf(WK[3*r+1], xe1, fmaf(WK[3*r+2], xe2, BK[r])));
                ko[r] = fmaf(WK[3*r], xo0, fmaf(WK[3*r+1], xo1, fmaf(WK[3*r+2], xo2, BK[r])));
                ve[r] = fmaf(WV[3*r], xe0, fmaf(WV[3*r+1], xe1, fmaf(WV[3*r+2], xe2, BV[r])));
                vo[r] = fmaf(WV[3*r], xo0, fmaf(WV[3*r+1], xo1, fmaf(WV[3*r+2], xo2, BV[r])));
            }
            sP[j] = make_float4(ke[0], ko[0], ke[1], ko[1]);
            sQ[j] = make_float4(ke[2], ko[2], ve[0], vo[0]);
            sR[j] = make_float4(ve[1], vo[1], ve[2], vo[2]);
        }
    }

    // ---- project both own queries (tokens 2u, 2u+1) ----
    ull qa0, qa1, qa2, qb0, qb1, qb2;
    {
        const float2* xp = (const float2*)(xb + 6 * u);
        float2 u0 = __ldg(&xp[0]);
        float2 u1 = __ldg(&xp[1]);
        float2 u2 = __ldg(&xp[2]);
        float ax0 = u0.x, ax1 = u0.y * inv0, ax2 = u1.x * inv1;
        float bx0 = u1.y, bx1 = u2.x * inv0, bx2 = u2.y * inv1;
        float W0 = __ldg(&ipw[0]), W1 = __ldg(&ipw[1]), W2 = __ldg(&ipw[2]);
        float W3 = __ldg(&ipw[3]), W4 = __ldg(&ipw[4]), W5 = __ldg(&ipw[5]);
        float W6 = __ldg(&ipw[6]), W7 = __ldg(&ipw[7]), W8 = __ldg(&ipw[8]);
        float B0 = __ldg(&ipb[0]), B1v = __ldg(&ipb[1]), B2v = __ldg(&ipb[2]);
        float a0 = fmaf(W0, ax0, fmaf(W1, ax1, fmaf(W2, ax2, B0))) * QS_C;
        float a1 = fmaf(W3, ax0, fmaf(W4, ax1, fmaf(W5, ax2, B1v))) * QS_C;
        float a2 = fmaf(W6, ax0, fmaf(W7, ax1, fmaf(W8, ax2, B2v))) * QS_C;
        float b0 = fmaf(W0, bx0, fmaf(W1, bx1, fmaf(W2, bx2, B0))) * QS_C;
        float b1 = fmaf(W3, bx0, fmaf(W4, bx1, fmaf(W5, bx2, B1v))) * QS_C;
        float b2 = fmaf(W6, bx0, fmaf(W7, bx1, fmaf(W8, bx2, B2v))) * QS_C;
        qa0 = pk2(a0, a0); qa1 = pk2(a1, a1); qa2 = pk2(a2, a2);
        qb0 = pk2(b0, b0); qb1 = pk2(b1, b1); qb2 = pk2(b2, b2);
    }

    __syncthreads();

    // ---- warp-uniform bulk bound + per-lane diagonal band ----
    const int ubase = c * UPC + (t & ~31);              // warp's min query-pair
    const int B1 = min(segl, max(0, ubase - s0));       // pairs fully valid for all lanes
    const int B2 = min(segl, max(0, ubase + 32 - s0));  // band end

    const ulonglong2* pP = (const ulonglong2*)sP;
    const ulonglong2* pQ = (const ulonglong2*)sQ;
    const ulonglong2* pR = (const ulonglong2*)sR;

    ull sumA = 0ull, a0A = 0ull, a1A = 0ull, a2A = 0ull;   // query qa
    ull sumB = 0ull, a0B = 0ull, a1B = 0ull, a2B = 0ull;   // query qb

    #pragma unroll 2
    for (int j = 0; j < B1; j++) {                      // unmasked bulk: 4 visits/iter
        ulonglong2 Pv = pP[j];
        ulonglong2 Qv = pQ[j];
        ulonglong2 Rv = pR[j];
        ull sa = fma2(Pv.x, qa0, fma2(Pv.y, qa1, mul2(Qv.x, qa2)));
        ull sb = fma2(Pv.x, qb0, fma2(Pv.y, qb1, mul2(Qv.x, qb2)));
        float sae, sao, sbe, sbo;
        up2(sa, sae, sao);
        up2(sb, sbe, sbo);
        ull pa = pk2(ex2f(sae), ex2f(sao));
        ull pb = pk2(ex2f(sbe), ex2f(sbo));
        sumA = add2(sumA, pa);
        a0A = fma2(pa, Qv.y, a0A);
        a1A = fma2(pa, Rv.x, a1A);
        a2A = fma2(pa, Rv.y, a2A);
        sumB = add2(sumB, pb);
        a0B = fma2(pb, Qv.y, a0B);
        a1B = fma2(pb, Rv.x, a1B);
        a2B = fma2(pb, Rv.y, a2B);
    }
    for (int j = B1; j < B2; j++) {                     // diagonal band (<=32 iters)
        int ja = s0 + j;                                // absolute pair id
        ulonglong2 Pv = pP[j];
        ulonglong2 Qv = pQ[j];
        ulonglong2 Rv = pR[j];
        ull sa = fma2(Pv.x, qa0, fma2(Pv.y, qa1, mul2(Qv.x, qa2)));
        ull sb = fma2(Pv.x, qb0, fma2(Pv.y, qb1, mul2(Qv.x, qb2)));
        float sae, sao, sbe, sbo;
        up2(sa, sae, sao);
        up2(sb, sbe, sbo);
        // qa=2u: even key valid iff ja<=u, odd iff ja<u ; qb=2u+1: both iff ja<=u
        ull pa = pk2((ja <= u) ? ex2f(sae) : 0.0f, (ja < u) ? ex2f(sao) : 0.0f);
        ull pb = (ja <= u) ? pk2(ex2f(sbe), ex2f(sbo)) : 0ull;
        sumA = add2(sumA, pa);
        a0A = fma2(pa, Qv.y, a0A);
        a1A = fma2(pa, Rv.x, a1A);
        a2A = fma2(pa, Rv.y, a2A);
        sumB = add2(sumB, pb);
        a0B = fma2(pb, Qv.y, a0B);
        a1B = fma2(pb, Rv.x, a1B);
        a2B = fma2(pb, Rv.y, a2B);
    }

    {
        float sl, sh, c0l, c0h, c1l, c1h, c2l, c2h;
        up2(sumA, sl, sh); up2(a0A, c0l, c0h); up2(a1A, c1l, c1h); up2(a2A, c2l, c2h);
        g_part[b][2*u][s] = make_float4(sl + sh, c0l + c0h, c1l + c1h, c2l + c2h);
        up2(sumB, sl, sh); up2(a0B, c0l, c0h); up2(a1B, c1l, c1h); up2(a2B, c2l, c2h);
        g_part[b][2*u+1][s] = make_float4(sl + sh, c0l + c0h, c1l + c1h, c2l + c2h);
    }

    // ---- last-arriver combine + epilogue (acq_rel atomic; no membar) ----
    unsigned old;
    asm volatile("atom.acq_rel.gpu.global.add.u32 %0, [%1], %2;"
                 : "=r"(old) : "l"(&g_cnt[b][u]), "r"(1u) : "memory");
    if (old == NSEG - 1) {
        g_cnt[b][u] = 0;                               // reset for next replay

        const float sc0 = __ldg(&sig[0]) + EPS_C;
        const float sc1 = __ldg(&sig[1]) + EPS_C;
        float wo[9];
        #pragma unroll
        for (int i = 0; i < 9; i++) wo[i] = __ldg(&opw[i]);
        const float bo1 = __ldg(&opb[1]), bo2 = __ldg(&opb[2]);
        const float m1 = __ldg(m1p), m2 = __ldg(m2p);
        float F1[3], F2[3], G1[3], G2[3];
        #pragma unroll
        for (int i = 0; i < 3; i++) {
            F1[i] = __ldg(&f1w[i]); F2[i] = __ldg(&f2w[i]);
            G1[i] = __ldg(&g1w[i]); G2[i] = __ldg(&g2w[i]);
        }
        const float F1b = __ldg(f1b), F2b = __ldg(f2b), G1b = __ldg(g1b), G2b = __ldg(g2b);

        #pragma unroll
        for (int tok = 0; tok < 2; tok++) {
            const int q = 2 * u + tok;
            const float4* gp = g_part[b][q];
            float cs = 0.f, c0 = 0.f, c1 = 0.f, c2 = 0.f;
            #pragma unroll
            for (int i = 0; i < NSEG; i++) {
                float4 P = gp[i];
                cs += P.x; c0 += P.y; c1 += P.z; c2 += P.w;
            }

            float inv = 1.0f / cs;
            float x0 = c0 * inv, x1 = c1 * inv, x2 = c2 * inv;
            float s1v = fmaf(wo[3], x0, fmaf(wo[4], x1, fmaf(wo[5], x2, bo1)));
            float s2v = fmaf(wo[6], x0, fmaf(wo[7], x1, fmaf(wo[8], x2, bo2)));

            float S2_1, S2_2, S3_1, S3_2, S4_1, S4_2;
            {
                float g1v = (G1[0] + fmaf(G1[1], s1v, fmaf(G1[2], s2v, G1b))) * m1;
                float g2v = (G2[0] + fmaf(G2[1], s1v, fmaf(G2[2], s2v, G2b))) * m2;
                S2_1 = fmaf(g1v, DT_C, s1v); S2_2 = fmaf(g2v, DT_C, s2v);
            }
            {
                float g1v = (G1[0] + fmaf(G1[1], S2_1, fmaf(G1[2], S2_2, G1b))) * m1;
                float g2v = (G2[0] + fmaf(G2[1], S2_1, fmaf(G2[2], S2_2, G2b))) * m2;
                S3_1 = fmaf(g1v, DT_C, S2_1); S3_2 = fmaf(g2v, DT_C, S2_2);
            }
            {
                float g1v = (G1[0] + fmaf(G1[1], S3_1, fmaf(G1[2], S3_2, G1b))) * m1;
                float g2v = (G2[0] + fmaf(G2[1], S3_1, fmaf(G2[2], S3_2, G2b))) * m2;
                S4_1 = fmaf(g1v, DT_C, S3_1); S4_2 = fmaf(g2v, DT_C, S3_2);
            }
            float vd1 = (F1[0] + fmaf(F1[1], S4_1, fmaf(F1[2], S4_2, F1b))) * m1;
            float vd2 = (F2[0] + fmaf(F2[1], S4_1, fmaf(F2[2], S4_2, F2b))) * m2;

            float4* o = (float4*)(out + (((size_t)b * LSEQ + q) << 3));
            o[0] = make_float4(S2_1 * sc0, S2_2 * sc1, S3_1 * sc0, S3_2 * sc1);
            o[1] = make_float4(S4_1 * sc0, S4_2 * sc1,
                               fmaf(vd1, DT_C, S4_1) * sc0, fmaf(vd2, DT_C, S4_2) * sc1);
        }
    }
}

extern "C" void kernel_launch(void* const* d_in, const int* in_sizes, int n_in,
                              void* d_out, int out_size)
{
    const float* inp = (const float*)d_in[1];
    const float* ipw = (const float*)d_in[2];
    const float* ipb = (const float*)d_in[3];
    const float* opw = (const float*)d_in[4];
    const float* opb = (const float*)d_in[5];
    const float* f1w = (const float*)d_in[6];
    const float* f1b = (const float*)d_in[7];
    const float* f2w = (const float*)d_in[8];
    const float* f2b = (const float*)d_in[9];
    const float* g1w = (const float*)d_in[10];
    const float* g1b = (const float*)d_in[11];
    const float* g2w = (const float*)d_in[12];
    const float* g2b = (const float*)d_in[13];
    const float* m1p = (const float*)d_in[14];
    const float* m2p = (const float*)d_in[15];
    const float* sig = (const float*)d_in[16];
    float* out = (float*)d_out;

    dim3 grid(BATCH, NSEG, NCHUNK);
    attn_kernel<<<grid, TPB>>>(inp, ipw, ipb, opw, opb,
                               f1w, f1b, f2w, f2b,
                               g1w, g1b, g2w, g2b,
                               m1p, m2p, sig, out);
}

// round 12
// speedup vs baseline: 1.1443x; 1.1443x over previous
#include <cuda_runtime.h>

#define LSEQ    2048
#define BATCH   32
#define NPAIR   1024
#define TPB     128
#define NCHUNK  16
#define NSEG    4
#define SEGMAX  256
#define DT_C    0.01f
#define EPS_C   1e-5f
#define QS_C    (1.4426950408889634f * 0.57735026918962576f)  // log2e/sqrt(3)

typedef unsigned long long ull;

__device__ __forceinline__ ull fma2(ull a, ull b, ull c) {
    ull d; asm("fma.rn.f32x2 %0, %1, %2, %3;" : "=l"(d) : "l"(a), "l"(b), "l"(c)); return d;
}
__device__ __forceinline__ ull mul2(ull a, ull b) {
    ull d; asm("mul.rn.f32x2 %0, %1, %2;" : "=l"(d) : "l"(a), "l"(b)); return d;
}
__device__ __forceinline__ ull add2(ull a, ull b) {
    ull d; asm("add.rn.f32x2 %0, %1, %2;" : "=l"(d) : "l"(a), "l"(b)); return d;
}
__device__ __forceinline__ ull pk2(float lo, float hi) {
    ull r; asm("mov.b64 %0, {%1, %2};" : "=l"(r) : "f"(lo), "f"(hi)); return r;
}
__device__ __forceinline__ void up2(ull v, float& lo, float& hi) {
    asm("mov.b64 {%0, %1}, %2;" : "=f"(lo), "=f"(hi) : "l"(v));
}
__device__ __forceinline__ float ex2f(float x) {
    float y; asm("ex2.approx.ftz.f32 %0, %1;" : "=f"(y) : "f"(x)); return y;
}

// partials [b][q][seg] = (sum, y1, y2, 0); counters zero-init, reset by winner
__device__ float4   g_part[BATCH][LSEQ][NSEG];
__device__ unsigned g_cnt[BATCH][LSEQ];

__global__ void __launch_bounds__(TPB, 8)
attn_kernel(const float* __restrict__ inp,
            const float* __restrict__ ipw, const float* __restrict__ ipb,
            const float* __restrict__ opw, const float* __restrict__ opb,
            const float* __restrict__ f1w, const float* __restrict__ f1b,
            const float* __restrict__ f2w, const float* __restrict__ f2b,
            const float* __restrict__ g1w, const float* __restrict__ g1b,
            const float* __restrict__ g2w, const float* __restrict__ g2b,
            const float* __restrict__ m1p, const float* __restrict__ m2p,
            const float* __restrict__ sig,
            float* __restrict__ out)
{
    __shared__ float4 sP[SEGMAX];   // (k0e,k0o,k1e,k1o)
    __shared__ float4 sQ[SEGMAX];   // (k2e,k2o,y1e,y1o)
    __shared__ float2 sY[SEGMAX];   // (y2e,y2o)

    const int b = blockIdx.x;
    const int s = blockIdx.y;
    const int c = (NCHUNK - 1) - blockIdx.z;        // long chunks first
    const int t = threadIdx.x;
    const int q = c * TPB + t;

    const int segl = (c + 1) * (NPAIR / NCHUNK / NSEG);   // (c+1)*16
    const int s0 = s * segl;

    const float inv0 = 1.0f / (__ldg(&sig[0]) + EPS_C);
    const float inv1 = 1.0f / (__ldg(&sig[1]) + EPS_C);
    const float* xb = inp + ((size_t)b * LSEQ) * 3;

    // ---- stage: project K and (Wo-fused) Y for this segment's pairs ----
    {
        float WK[9], BK[3], WV[9], BV[3];
        #pragma unroll
        for (int k = 0; k < 9; k++) { WK[k] = __ldg(&ipw[9 + k]); WV[k] = __ldg(&ipw[18 + k]); }
        #pragma unroll
        for (int k = 0; k < 3; k++) { BK[k] = __ldg(&ipb[3 + k]); BV[k] = __ldg(&ipb[6 + k]); }
        // fold out-proj rows 1,2 into V: y_r = WY[r]·x + BY[r]
        float WY[6], BY[2];
        #pragma unroll
        for (int r = 0; r < 2; r++) {
            float w0 = __ldg(&opw[3 + 3*r + 0]);
            float w1 = __ldg(&opw[3 + 3*r + 1]);
            float w2 = __ldg(&opw[3 + 3*r + 2]);
            #pragma unroll
            for (int cc = 0; cc < 3; cc++)
                WY[3*r + cc] = w0 * WV[cc] + w1 * WV[3 + cc] + w2 * WV[6 + cc];
            BY[r] = w0 * BV[0] + w1 * BV[1] + w2 * BV[2];
        }

        for (int j = t; j < segl; j += TPB) {
            const float2* xp = (const float2*)(xb + 6 * (s0 + j));
            float2 u0 = __ldg(&xp[0]);
            float2 u1 = __ldg(&xp[1]);
            float2 u2 = __ldg(&xp[2]);
            float xe0 = u0.x, xe1 = u0.y * inv0, xe2 = u1.x * inv1;
            float xo0 = u1.y, xo1 = u2.x * inv0, xo2 = u2.y * inv1;
            float ke[3], ko[3];
            #pragma unroll
            for (int r = 0; r < 3; r++) {
                ke[r] = fmaf(WK[3*r], xe0, fmaf(WK[3*r+1], xe1, fmaf(WK[3*r+2], xe2, BK[r])));
                ko[r] = fmaf(WK[3*r], xo0, fmaf(WK[3*r+1], xo1, fmaf(WK[3*r+2], xo2, BK[r])));
            }
            float y1e = fmaf(WY[0], xe0, fmaf(WY[1], xe1, fmaf(WY[2], xe2, BY[0])));
            float y1o = fmaf(WY[0], xo0, fmaf(WY[1], xo1, fmaf(WY[2], xo2, BY[0])));
            float y2e = fmaf(WY[3], xe0, fmaf(WY[4], xe1, fmaf(WY[5], xe2, BY[1])));
            float y2o = fmaf(WY[3], xo0, fmaf(WY[4], xo1, fmaf(WY[5], xo2, BY[1])));
            sP[j] = make_float4(ke[0], ko[0], ke[1], ko[1]);
            sQ[j] = make_float4(ke[2], ko[2], y1e, y1o);
            sY[j] = make_float2(y2e, y2o);
        }
    }

    // ---- own query ----
    ull qp0, qp1, qp2;
    {
        const float* xq = xb + q * 3;
        float x0 = __ldg(&xq[0]), x1 = __ldg(&xq[1]) * inv0, x2 = __ldg(&xq[2]) * inv1;
        float q0 = fmaf(__ldg(&ipw[0]), x0, fmaf(__ldg(&ipw[1]), x1, fmaf(__ldg(&ipw[2]), x2, __ldg(&ipb[0])))) * QS_C;
        float q1 = fmaf(__ldg(&ipw[3]), x0, fmaf(__ldg(&ipw[4]), x1, fmaf(__ldg(&ipw[5]), x2, __ldg(&ipb[1])))) * QS_C;
        float q2 = fmaf(__ldg(&ipw[6]), x0, fmaf(__ldg(&ipw[7]), x1, fmaf(__ldg(&ipw[8]), x2, __ldg(&ipb[2])))) * QS_C;
        qp0 = pk2(q0, q0); qp1 = pk2(q1, q1); qp2 = pk2(q2, q2);
    }

    __syncthreads();

    // causal bounds (relative j; absolute pair id gp = s0 + j)
    const int qbase = c * TPB + (t & ~31);
    const int lbmin = (qbase - 1) >> 1;
    const int lamax = (qbase + 31) >> 1;
    const int B1 = min(segl, max(0, lbmin + 1 - s0));   // unmasked for all lanes
    const int B2 = min(segl, max(0, lamax + 1 - s0));   // diagonal band end
    const int la = q >> 1;
    const int lb = (q - 1) >> 1;

    const ulonglong2* pP = (const ulonglong2*)sP;
    const ulonglong2* pQ = (const ulonglong2*)sQ;
    const ull* pY = (const ull*)sY;

    ull sum2 = 0ull, y12 = 0ull, y22 = 0ull;

    #pragma unroll 4
    for (int j = 0; j < B1; j++) {                  // unmasked bulk: 11 slots
        ulonglong2 Pv = pP[j];
        ulonglong2 Qv = pQ[j];
        ull Yv = pY[j];
        ull sc = fma2(Pv.x, qp0, fma2(Pv.y, qp1, mul2(Qv.x, qp2)));
        float se, so; up2(sc, se, so);
        ull p = pk2(ex2f(se), ex2f(so));
        sum2 = add2(sum2, p);
        y12 = fma2(p, Qv.y, y12);
        y22 = fma2(p, Yv, y22);
    }
    for (int j = B1; j < B2; j++) {                 // diagonal band (<=17 iters)
        int gp = s0 + j;
        ulonglong2 Pv = pP[j];
        ulonglong2 Qv = pQ[j];
        ull Yv = pY[j];
        ull sc = fma2(Pv.x, qp0, fma2(Pv.y, qp1, mul2(Qv.x, qp2)));
        float se, so; up2(sc, se, so);
        float plo = (gp <= la) ? ex2f(se) : 0.0f;
        float phi = (gp <= lb) ? ex2f(so) : 0.0f;
        ull p = pk2(plo, phi);
        sum2 = add2(sum2, p);
        y12 = fma2(p, Qv.y, y12);
        y22 = fma2(p, Yv, y22);
    }

    float sl, sh, y1l, y1h, y2l, y2h;
    up2(sum2, sl, sh); up2(y12, y1l, y1h); up2(y22, y2l, y2h);
    g_part[b][q][s] = make_float4(sl + sh, y1l + y1h, y2l + y2h, 0.0f);

    // ---- last-arriver combine + epilogue ----
    unsigned old;
    asm volatile("atom.acq_rel.gpu.global.add.u32 %0, [%1], %2;"
                 : "=r"(old) : "l"(&g_cnt[b][q]), "r"(1u) : "memory");
    if (old == NSEG - 1) {
        g_cnt[b][q] = 0;                            // reset for next replay

        const float4* gp = g_part[b][q];
        float4 A = gp[0], Bp = gp[1], C = gp[2], D = gp[3];
        float cs = (A.x + Bp.x) + (C.x + D.x);
        float y1 = (A.y + Bp.y) + (C.y + D.y);
        float y2 = (A.z + Bp.z) + (C.z + D.z);

        const float sc0 = __ldg(&sig[0]) + EPS_C;
        const float sc1 = __ldg(&sig[1]) + EPS_C;
        const float bo1 = __ldg(&opb[1]), bo2 = __ldg(&opb[2]);
        const float m1 = __ldg(m1p), m2 = __ldg(m2p);
        float F1[3], F2[3], G1[3], G2[3];
        #pragma unroll
        for (int i = 0; i < 3; i++) {
            F1[i] = __ldg(&f1w[i]); F2[i] = __ldg(&f2w[i]);
            G1[i] = __ldg(&g1w[i]); G2[i] = __ldg(&g2w[i]);
        }
        const float F1b = __ldg(f1b), F2b = __ldg(f2b), G1b = __ldg(g1b), G2b = __ldg(g2b);

        float inv = 1.0f / cs;
        float s1v = fmaf(y1, inv, bo1);
        float s2v = fmaf(y2, inv, bo2);

        float S2_1, S2_2, S3_1, S3_2, S4_1, S4_2;
        {
            float g1v = (G1[0] + fmaf(G1[1], s1v, fmaf(G1[2], s2v, G1b))) * m1;
            float g2v = (G2[0] + fmaf(G2[1], s1v, fmaf(G2[2], s2v, G2b))) * m2;
            S2_1 = fmaf(g1v, DT_C, s1v); S2_2 = fmaf(g2v, DT_C, s2v);
        }
        {
            float g1v = (G1[0] + fmaf(G1[1], S2_1, fmaf(G1[2], S2_2, G1b))) * m1;
            float g2v = (G2[0] + fmaf(G2[1], S2_1, fmaf(G2[2], S2_2, G2b))) * m2;
            S3_1 = fmaf(g1v, DT_C, S2_1); S3_2 = fmaf(g2v, DT_C, S2_2);
        }
        {
            float g1v = (G1[0] + fmaf(G1[1], S3_1, fmaf(G1[2], S3_2, G1b))) * m1;
            float g2v = (G2[0] + fmaf(G2[1], S3_1, fmaf(G2[2], S3_2, G2b))) * m2;
            S4_1 = fmaf(g1v, DT_C, S3_1); S4_2 = fmaf(g2v, DT_C, S3_2);
        }
        float vd1 = (F1[0] + fmaf(F1[1], S4_1, fmaf(F1[2], S4_2, F1b))) * m1;
        float vd2 = (F2[0] + fmaf(F2[1], S4_1, fmaf(F2[2], S4_2, F2b))) * m2;

        float4* o = (float4*)(out + (((size_t)b * LSEQ + q) << 3));
        o[0] = make_float4(S2_1 * sc0, S2_2 * sc1, S3_1 * sc0, S3_2 * sc1);
        o[1] = make_float4(S4_1 * sc0, S4_2 * sc1,
                           fmaf(vd1, DT_C, S4_1) * sc0, fmaf(vd2, DT_C, S4_2) * sc1);
    }
}

extern "C" void kernel_launch(void* const* d_in, const int* in_sizes, int n_in,
                              void* d_out, int out_size)
{
    const float* inp = (const float*)d_in[1];
    const float* ipw = (const float*)d_in[2];
    const float* ipb = (const float*)d_in[3];
    const float* opw = (const float*)d_in[4];
    const float* opb = (const float*)d_in[5];
    const float* f1w = (const float*)d_in[6];
    const float* f1b = (const float*)d_in[7];
    const float* f2w = (const float*)d_in[8];
    const float* f2b = (const float*)d_in[9];
    const float* g1w = (const float*)d_in[10];
    const float* g1b = (const float*)d_in[11];
    const float* g2w = (const float*)d_in[12];
    const float* g2b = (const float*)d_in[13];
    const float* m1p = (const float*)d_in[14];
    const float* m2p = (const float*)d_in[15];
    const float* sig = (const float*)d_in[16];
    float* out = (float*)d_out;

    dim3 grid(BATCH, NSEG, NCHUNK);
    attn_kernel<<<grid, TPB>>>(inp, ipw, ipb, opw, opb,
                               f1w, f1b, f2w, f2b,
                               g1w, g1b, g2w, g2b,
                               m1p, m2p, sig, out);
}